// round 7
// baseline (speedup 1.0000x reference)
#include <cuda_runtime.h>
#include <cuda_bf16.h>
#include <cuda_fp16.h>
#include <cstdint>

// ======================= problem sizes (fixed by dataset) ====================
#define TOKENS 4096
#define IC     4096
#define OC     4096
#define NOUTP  256   // outlier columns padded 204 -> 256

// ======================= device scratch (no runtime alloc) ==================
__device__ uint16_t g_x16[(size_t)TOKENS * IC];     // 32 MB  x as fp16
__device__ uint16_t g_s16[(size_t)OC * IC];         // 32 MB  sign matrix fp16
__device__ uint16_t g_xo16[(size_t)TOKENS * NOUTP]; // fp16 gathered outlier x
__device__ uint16_t g_ow16[(size_t)OC * NOUTP];     // fp16 (ow / s_o)
__device__ float g_scale[OC];   // 0 -> 1 (exact: then all signs are 0)
__device__ int   g_map[IC];

// ======================= helpers =============================================
__device__ __forceinline__ uint32_t smem_u32(const void* p) {
    uint32_t a;
    asm("{ .reg .u64 t; cvta.to.shared.u64 t, %1; cvt.u32.u64 %0, t; }"
        : "=r"(a) : "l"(p));
    return a;
}

#define CP_ASYNC16(saddr, gaddr) \
    asm volatile("cp.async.cg.shared.global [%0], [%1], 16;" \
                 :: "r"(saddr), "l"(gaddr))
#define CP_COMMIT() asm volatile("cp.async.commit_group;" ::: "memory")
#define CP_WAIT2()  asm volatile("cp.async.wait_group 2;" ::: "memory")

#define LDMATRIX_X4(r0, r1, r2, r3, addr) \
    asm volatile("ldmatrix.sync.aligned.m8n8.x4.shared.b16 {%0,%1,%2,%3}, [%4];" \
                 : "=r"(r0), "=r"(r1), "=r"(r2), "=r"(r3) : "r"(addr))

#define MMA_F16(d, a, b0, b1) \
    asm volatile("mma.sync.aligned.m16n8k16.row.col.f32.f16.f16.f32 " \
                 "{%0,%1,%2,%3}, {%4,%5,%6,%7}, {%8,%9}, {%0,%1,%2,%3};" \
                 : "+f"((d)[0]), "+f"((d)[1]), "+f"((d)[2]), "+f"((d)[3]) \
                 : "r"((a)[0]), "r"((a)[1]), "r"((a)[2]), "r"((a)[3]), \
                   "r"(b0), "r"(b1))

// ======================= prep kernels ========================================
__global__ void map_init_kernel() {
    int i = blockIdx.x * 256 + threadIdx.x;
    if (i < IC) g_map[i] = -1;
}
__global__ void map_scatter_kernel(const int* __restrict__ idx, int nout) {
    int j = blockIdx.x * 256 + threadIdx.x;
    if (j < nout) g_map[idx[j]] = j;
}

// Fused: per-row mean & abs-mean of w + write fp16 sign row (outlier cols 0).
__global__ void stats_ws_kernel(const float* __restrict__ w) {
    __shared__ float red[256];
    int o = blockIdx.x, tid = threadIdx.x;
    const float4* row = (const float4*)(w + (size_t)o * IC);
    float4 v[4];
    float s = 0.f;
#pragma unroll
    for (int i = 0; i < 4; ++i) {
        v[i] = row[tid + 256 * i];
        s += v[i].x + v[i].y + v[i].z + v[i].w;
    }
    red[tid] = s;
    __syncthreads();
    for (int st = 128; st > 0; st >>= 1) {
        if (tid < st) red[tid] += red[tid + st];
        __syncthreads();
    }
    float mean = red[0] * (1.f / IC);
    __syncthreads();
    float a = 0.f;
#pragma unroll
    for (int i = 0; i < 4; ++i)
        a += fabsf(v[i].x - mean) + fabsf(v[i].y - mean) +
             fabsf(v[i].z - mean) + fabsf(v[i].w - mean);
    red[tid] = a;
    __syncthreads();
    for (int st = 128; st > 0; st >>= 1) {
        if (tid < st) red[tid] += red[tid + st];
        __syncthreads();
    }
    if (tid == 0) {
        float sc = red[0] * (1.f / IC);
        g_scale[o] = (sc == 0.f) ? 1.f : sc;
    }
#pragma unroll
    for (int i = 0; i < 4; ++i) {
        int e0 = (tid + 256 * i) * 4;
        float ev[4] = {v[i].x, v[i].y, v[i].z, v[i].w};
        uint16_t hv[4];
#pragma unroll
        for (int e = 0; e < 4; ++e) {
            float sv = 0.f;
            if (g_map[e0 + e] < 0) {
                float wc = ev[e] - mean;
                sv = (wc > 0.f) ? 1.f : ((wc < 0.f) ? -1.f : 0.f);
            }
            hv[e] = __half_as_ushort(__float2half_rn(sv));
        }
        uint2 pk;
        pk.x = (uint32_t)hv[0] | ((uint32_t)hv[1] << 16);
        pk.y = (uint32_t)hv[2] | ((uint32_t)hv[3] << 16);
        *(uint2*)(g_s16 + (size_t)o * IC + e0) = pk;
    }
}

__global__ void build_x_kernel(const float* __restrict__ x) {
    size_t base = ((size_t)blockIdx.x * 256 + threadIdx.x) * 8;
    float4 v0 = *(const float4*)(x + base);
    float4 v1 = *(const float4*)(x + base + 4);
    float e[8] = {v0.x, v0.y, v0.z, v0.w, v1.x, v1.y, v1.z, v1.w};
    uint16_t hv[8];
#pragma unroll
    for (int k = 0; k < 8; ++k) hv[k] = __half_as_ushort(__float2half_rn(e[k]));
    uint4 pk;
    pk.x = (uint32_t)hv[0] | ((uint32_t)hv[1] << 16);
    pk.y = (uint32_t)hv[2] | ((uint32_t)hv[3] << 16);
    pk.z = (uint32_t)hv[4] | ((uint32_t)hv[5] << 16);
    pk.w = (uint32_t)hv[6] | ((uint32_t)hv[7] << 16);
    *(uint4*)(g_x16 + base) = pk;
}

__global__ void build_xout_kernel(const float* __restrict__ x,
                                  const int* __restrict__ idx, int nout) {
    int g = blockIdx.x * 256 + threadIdx.x;
    if (g >= TOKENS * NOUTP / 4) return;
    int tok = g >> 6;
    int j0 = (g & 63) * 4;
    uint16_t hv[4];
#pragma unroll
    for (int e = 0; e < 4; ++e) {
        int j = j0 + e;
        float xv = (j < nout) ? x[(size_t)tok * IC + idx[j]] : 0.f;
        hv[e] = __half_as_ushort(__float2half_rn(xv));
    }
    *(uint2*)(g_xo16 + (size_t)tok * NOUTP + j0) =
        make_uint2((uint32_t)hv[0] | ((uint32_t)hv[1] << 16),
                   (uint32_t)hv[2] | ((uint32_t)hv[3] << 16));
}

__global__ void build_ow_kernel(const float* __restrict__ ow, int nout) {
    int g = blockIdx.x * 256 + threadIdx.x;
    if (g >= OC * NOUTP / 4) return;
    int o = g >> 6;
    int j0 = (g & 63) * 4;
    float inv_s = 1.f / g_scale[o];
    uint16_t hv[4];
#pragma unroll
    for (int e = 0; e < 4; ++e) {
        int j = j0 + e;
        float v = (j < nout) ? ow[(size_t)o * nout + j] * inv_s : 0.f;
        hv[e] = __half_as_ushort(__float2half_rn(v));
    }
    *(uint2*)(g_ow16 + (size_t)o * NOUTP + j0) =
        make_uint2((uint32_t)hv[0] | ((uint32_t)hv[1] << 16),
                   (uint32_t)hv[2] | ((uint32_t)hv[3] << 16));
}

// ======================= fused GEMM ==========================================
// CTA 64(tokens) x 128(out-ch), BK=64, 4 stages, 2 CTAs/SM, ONE barrier/iter.
// 8 warps (2m x 4n), warp tile 32x32, all fp16 mma.
//   kt 0..63 : A=x16,  B=s16   (binary, K=4096)
//   kt 64..67: A=xo16, B=ow16  (outliers, K=256)
// Epilogue: out = acc * s_o + bias.
static constexpr int NT = 68;
static constexpr int STAGE_BYTES = (64 + 128) * 64 * 2;  // 24576
static constexpr int OFF_B = 64 * 64 * 2;                 // 8192
static constexpr int SMEM_BYTES = 4 * STAGE_BYTES;        // 98304

__global__ void __launch_bounds__(256, 2)
gemm_kernel(float* __restrict__ out, const float* __restrict__ bias) {
    extern __shared__ __align__(1024) char smem[];
    const uint32_t sbase = smem_u32(smem);
    const int tid = threadIdx.x;
    const int bn = blockIdx.x, bm = blockIdx.y;
    const int wid = tid >> 5, lane = tid & 31;
    const int wm = wid >> 2, wn = wid & 3;

    float acc[2][4][4];
#pragma unroll
    for (int i = 0; i < 2; ++i)
#pragma unroll
        for (int j = 0; j < 4; ++j)
#pragma unroll
            for (int k = 0; k < 4; ++k) acc[i][j][k] = 0.f;

    // ---- stage loader: A 64x64 (2 chunks/thread), B 128x64 (4 chunks) --
    auto issue = [&](int kt, int s) {
        const uint16_t *a, *b;
        int stride;
        if (kt < 64) {
            int off = kt * 64;
            a = g_x16 + (size_t)bm * 64 * IC + off;
            b = g_s16 + (size_t)bn * 128 * IC + off;
            stride = IC;
        } else {
            int koff = (kt - 64) * 64;
            a = g_xo16 + (size_t)bm * 64 * NOUTP + koff;
            b = g_ow16 + (size_t)bn * 128 * NOUTP + koff;
            stride = NOUTP;
        }
        uint32_t st = sbase + s * STAGE_BYTES;
#pragma unroll
        for (int i = 0; i < 2; ++i) {
            int c = tid + i * 256;
            int row = c >> 3, ch = c & 7;
            uint32_t so = (uint32_t)row * 128 + (uint32_t)((ch ^ (row & 7)) << 4);
            CP_ASYNC16(st + so, a + (size_t)row * stride + ch * 8);
        }
#pragma unroll
        for (int i = 0; i < 4; ++i) {
            int c = tid + i * 256;
            int row = c >> 3, ch = c & 7;
            uint32_t so = (uint32_t)row * 128 + (uint32_t)((ch ^ (row & 7)) << 4);
            CP_ASYNC16(st + OFF_B + so, b + (size_t)row * stride + ch * 8);
        }
    };

    // ---- compute on one stage ------------------------------------------
    auto compute = [&](int s) {
        uint32_t stA = sbase + s * STAGE_BYTES;
        uint32_t stB = stA + OFF_B;
#pragma unroll
        for (int ks = 0; ks < 4; ++ks) {
            uint32_t bfr[2][4];
#pragma unroll
            for (int nj = 0; nj < 2; ++nj) {
                int row = wn * 32 + nj * 16 + (lane & 7) + (((lane >> 4) & 1) << 3);
                int ch = ks * 2 + ((lane >> 3) & 1);
                uint32_t ad = stB + (uint32_t)row * 128 +
                              (uint32_t)((ch ^ (row & 7)) << 4);
                LDMATRIX_X4(bfr[nj][0], bfr[nj][1], bfr[nj][2], bfr[nj][3], ad);
            }
            uint32_t afr[2][4];
#pragma unroll
            for (int mi = 0; mi < 2; ++mi) {
                int row = wm * 32 + mi * 16 + (lane & 15);
                int ch = ks * 2 + (lane >> 4);
                uint32_t ad = stA + (uint32_t)row * 128 +
                              (uint32_t)((ch ^ (row & 7)) << 4);
                LDMATRIX_X4(afr[mi][0], afr[mi][1], afr[mi][2], afr[mi][3], ad);
            }
#pragma unroll
            for (int mi = 0; mi < 2; ++mi)
#pragma unroll
                for (int nf = 0; nf < 4; ++nf)
                    MMA_F16(acc[mi][nf], afr[mi],
                            bfr[nf >> 1][(nf & 1) * 2],
                            bfr[nf >> 1][(nf & 1) * 2 + 1]);
        }
    };

    // ---- multistage main loop: ONE barrier per iteration ----------------
    issue(0, 0); CP_COMMIT();
    issue(1, 1); CP_COMMIT();
    issue(2, 2); CP_COMMIT();
    for (int kt = 0; kt < NT; ++kt) {
        CP_WAIT2();
        __syncthreads();
        // safe: writes stage (kt+3)&3 == (kt-1)&3, consumed by all warps
        // before this barrier (their compute(kt-1) preceded it).
        if (kt + 3 < NT) issue(kt + 3, (kt + 3) & 3);
        CP_COMMIT();   // commit every iter keeps wait_group accounting exact
        compute(kt & 3);
    }

    // ---- epilogue: out = acc * s_o + bias ------------------------------
#pragma unroll
    for (int nf = 0; nf < 4; ++nf) {
        int col = bn * 128 + wn * 32 + (nf >> 1) * 16 + (nf & 1) * 8 + 2 * (lane & 3);
        float s0 = g_scale[col], s1 = g_scale[col + 1];
        float b0 = __ldg(bias + col), b1 = __ldg(bias + col + 1);
#pragma unroll
        for (int mi = 0; mi < 2; ++mi) {
            int r0 = bm * 64 + wm * 32 + mi * 16 + (lane >> 2);
            float2 v0 = make_float2(acc[mi][nf][0] * s0 + b0,
                                    acc[mi][nf][1] * s1 + b1);
            *(float2*)(out + (size_t)r0 * OC + col) = v0;
            float2 v1 = make_float2(acc[mi][nf][2] * s0 + b0,
                                    acc[mi][nf][3] * s1 + b1);
            *(float2*)(out + (size_t)(r0 + 8) * OC + col) = v1;
        }
    }
}

// ======================= launcher ============================================
extern "C" void kernel_launch(void* const* d_in, const int* in_sizes, int n_in,
                              void* d_out, int out_size) {
    const float* x = (const float*)d_in[0];
    const float* w = (const float*)d_in[1];
    const float* bias = (const float*)d_in[2];
    const float* ow = (const float*)d_in[3];
    const int* idx = (const int*)d_in[4];
    float* out = (float*)d_out;
    int nout = in_sizes[4];

    static bool attr_set = false;
    if (!attr_set) {
        cudaFuncSetAttribute(gemm_kernel,
                             cudaFuncAttributeMaxDynamicSharedMemorySize, SMEM_BYTES);
        attr_set = true;
    }

    map_init_kernel<<<IC / 256, 256>>>();
    map_scatter_kernel<<<(nout + 255) / 256, 256>>>(idx, nout);
    stats_ws_kernel<<<OC, 256>>>(w);
    build_x_kernel<<<(unsigned)((size_t)TOKENS * IC / 2048), 256>>>(x);
    build_xout_kernel<<<TOKENS * NOUTP / 4 / 256, 256>>>(x, idx, nout);
    build_ow_kernel<<<OC * NOUTP / 4 / 256, 256>>>(ow, nout);

    dim3 grid(OC / 128, TOKENS / 64);
    gemm_kernel<<<grid, 256, SMEM_BYTES>>>(out, bias);
}

// round 8
// speedup vs baseline: 1.1145x; 1.1145x over previous
#include <cuda_runtime.h>
#include <cuda_bf16.h>
#include <cuda_fp16.h>
#include <cstdint>

// ======================= problem sizes (fixed by dataset) ====================
#define TOKENS 4096
#define IC     4096
#define OC     4096
#define NOUTP  256   // outlier columns padded 204 -> 256

// Tile bookkeeping: 1024 = 32x32 tiles of 128x128. Tiles [0,888) -> big kernel
// (3.0 exact waves at 2 CTAs/SM on 148 SMs). Tiles [888,1024) -> small kernel,
// each split into 2 CTAs of 64x128 (272 CTAs = 0.92 waves).
#define N_BIG 888

// ======================= device scratch (no runtime alloc) ==================
__device__ uint16_t g_x16[(size_t)TOKENS * IC];     // 32 MB  x as fp16
__device__ uint16_t g_s16[(size_t)OC * IC];         // 32 MB  sign matrix fp16
__device__ uint16_t g_xo16[(size_t)TOKENS * NOUTP]; // fp16 gathered outlier x
__device__ uint16_t g_ow16[(size_t)OC * NOUTP];     // fp16 (ow / s_o)
__device__ float g_scale[OC];   // 0 -> 1 (exact: then all signs are 0)
__device__ int   g_map[IC];

// ======================= helpers =============================================
__device__ __forceinline__ uint32_t smem_u32(const void* p) {
    uint32_t a;
    asm("{ .reg .u64 t; cvta.to.shared.u64 t, %1; cvt.u32.u64 %0, t; }"
        : "=r"(a) : "l"(p));
    return a;
}

#define CP_ASYNC16(saddr, gaddr) \
    asm volatile("cp.async.cg.shared.global [%0], [%1], 16;" \
                 :: "r"(saddr), "l"(gaddr))
#define CP_COMMIT() asm volatile("cp.async.commit_group;" ::: "memory")
#define CP_WAIT2()  asm volatile("cp.async.wait_group 2;" ::: "memory")

#define LDMATRIX_X4(r0, r1, r2, r3, addr) \
    asm volatile("ldmatrix.sync.aligned.m8n8.x4.shared.b16 {%0,%1,%2,%3}, [%4];" \
                 : "=r"(r0), "=r"(r1), "=r"(r2), "=r"(r3) : "r"(addr))

#define MMA_F16(d, a, b0, b1) \
    asm volatile("mma.sync.aligned.m16n8k16.row.col.f32.f16.f16.f32 " \
                 "{%0,%1,%2,%3}, {%4,%5,%6,%7}, {%8,%9}, {%0,%1,%2,%3};" \
                 : "+f"((d)[0]), "+f"((d)[1]), "+f"((d)[2]), "+f"((d)[3]) \
                 : "r"((a)[0]), "r"((a)[1]), "r"((a)[2]), "r"((a)[3]), \
                   "r"(b0), "r"(b1))

// ======================= prep kernels ========================================
__global__ void map_init_kernel() {
    int i = blockIdx.x * 256 + threadIdx.x;
    if (i < IC) g_map[i] = -1;
}
__global__ void map_scatter_kernel(const int* __restrict__ idx, int nout) {
    int j = blockIdx.x * 256 + threadIdx.x;
    if (j < nout) g_map[idx[j]] = j;
}

// Fused: per-row mean & abs-mean of w + write fp16 sign row (outlier cols 0).
__global__ void stats_ws_kernel(const float* __restrict__ w) {
    __shared__ float red[256];
    int o = blockIdx.x, tid = threadIdx.x;
    const float4* row = (const float4*)(w + (size_t)o * IC);
    float4 v[4];
    float s = 0.f;
#pragma unroll
    for (int i = 0; i < 4; ++i) {
        v[i] = row[tid + 256 * i];
        s += v[i].x + v[i].y + v[i].z + v[i].w;
    }
    red[tid] = s;
    __syncthreads();
    for (int st = 128; st > 0; st >>= 1) {
        if (tid < st) red[tid] += red[tid + st];
        __syncthreads();
    }
    float mean = red[0] * (1.f / IC);
    __syncthreads();
    float a = 0.f;
#pragma unroll
    for (int i = 0; i < 4; ++i)
        a += fabsf(v[i].x - mean) + fabsf(v[i].y - mean) +
             fabsf(v[i].z - mean) + fabsf(v[i].w - mean);
    red[tid] = a;
    __syncthreads();
    for (int st = 128; st > 0; st >>= 1) {
        if (tid < st) red[tid] += red[tid + st];
        __syncthreads();
    }
    if (tid == 0) {
        float sc = red[0] * (1.f / IC);
        g_scale[o] = (sc == 0.f) ? 1.f : sc;
    }
#pragma unroll
    for (int i = 0; i < 4; ++i) {
        int e0 = (tid + 256 * i) * 4;
        float ev[4] = {v[i].x, v[i].y, v[i].z, v[i].w};
        uint16_t hv[4];
#pragma unroll
        for (int e = 0; e < 4; ++e) {
            float sv = 0.f;
            if (g_map[e0 + e] < 0) {
                float wc = ev[e] - mean;
                sv = (wc > 0.f) ? 1.f : ((wc < 0.f) ? -1.f : 0.f);
            }
            hv[e] = __half_as_ushort(__float2half_rn(sv));
        }
        uint2 pk;
        pk.x = (uint32_t)hv[0] | ((uint32_t)hv[1] << 16);
        pk.y = (uint32_t)hv[2] | ((uint32_t)hv[3] << 16);
        *(uint2*)(g_s16 + (size_t)o * IC + e0) = pk;
    }
}

__global__ void build_x_kernel(const float* __restrict__ x) {
    size_t base = ((size_t)blockIdx.x * 256 + threadIdx.x) * 8;
    float4 v0 = *(const float4*)(x + base);
    float4 v1 = *(const float4*)(x + base + 4);
    float e[8] = {v0.x, v0.y, v0.z, v0.w, v1.x, v1.y, v1.z, v1.w};
    uint16_t hv[8];
#pragma unroll
    for (int k = 0; k < 8; ++k) hv[k] = __half_as_ushort(__float2half_rn(e[k]));
    uint4 pk;
    pk.x = (uint32_t)hv[0] | ((uint32_t)hv[1] << 16);
    pk.y = (uint32_t)hv[2] | ((uint32_t)hv[3] << 16);
    pk.z = (uint32_t)hv[4] | ((uint32_t)hv[5] << 16);
    pk.w = (uint32_t)hv[6] | ((uint32_t)hv[7] << 16);
    *(uint4*)(g_x16 + base) = pk;
}

__global__ void build_xout_kernel(const float* __restrict__ x,
                                  const int* __restrict__ idx, int nout) {
    int g = blockIdx.x * 256 + threadIdx.x;
    if (g >= TOKENS * NOUTP / 4) return;
    int tok = g >> 6;
    int j0 = (g & 63) * 4;
    uint16_t hv[4];
#pragma unroll
    for (int e = 0; e < 4; ++e) {
        int j = j0 + e;
        float xv = (j < nout) ? x[(size_t)tok * IC + idx[j]] : 0.f;
        hv[e] = __half_as_ushort(__float2half_rn(xv));
    }
    *(uint2*)(g_xo16 + (size_t)tok * NOUTP + j0) =
        make_uint2((uint32_t)hv[0] | ((uint32_t)hv[1] << 16),
                   (uint32_t)hv[2] | ((uint32_t)hv[3] << 16));
}

__global__ void build_ow_kernel(const float* __restrict__ ow, int nout) {
    int g = blockIdx.x * 256 + threadIdx.x;
    if (g >= OC * NOUTP / 4) return;
    int o = g >> 6;
    int j0 = (g & 63) * 4;
    float inv_s = 1.f / g_scale[o];
    uint16_t hv[4];
#pragma unroll
    for (int e = 0; e < 4; ++e) {
        int j = j0 + e;
        float v = (j < nout) ? ow[(size_t)o * nout + j] * inv_s : 0.f;
        hv[e] = __half_as_ushort(__float2half_rn(v));
    }
    *(uint2*)(g_ow16 + (size_t)o * NOUTP + j0) =
        make_uint2((uint32_t)hv[0] | ((uint32_t)hv[1] << 16),
                   (uint32_t)hv[2] | ((uint32_t)hv[3] << 16));
}

// ======================= big GEMM (R6 config, 1D grid) =======================
// CTA 128x128, BK=64, 3 stages, 2 CTAs/SM. 8 warps (2m x 4n), warp tile 64x32.
static constexpr int NT = 68;
static constexpr int BSTAGE = (128 + 128) * 64 * 2;  // 32768
static constexpr int BOFF_B = 128 * 64 * 2;           // 16384
static constexpr int BSMEM  = 3 * BSTAGE;             // 98304

__global__ void __launch_bounds__(256, 2)
gemm_big_kernel(float* __restrict__ out, const float* __restrict__ bias) {
    extern __shared__ __align__(1024) char smem[];
    const uint32_t sbase = smem_u32(smem);
    const int tid = threadIdx.x;
    const int id = blockIdx.x;           // 0..887
    const int bm = id >> 5, bn = id & 31;
    const int wid = tid >> 5, lane = tid & 31;
    const int wm = wid >> 2, wn = wid & 3;

    float acc[4][4][4];
#pragma unroll
    for (int i = 0; i < 4; ++i)
#pragma unroll
        for (int j = 0; j < 4; ++j)
#pragma unroll
            for (int k = 0; k < 4; ++k) acc[i][j][k] = 0.f;

    auto issue = [&](int kt, int s) {
        const uint16_t *a, *b;
        int stride;
        if (kt < 64) {
            int off = kt * 64;
            a = g_x16 + (size_t)bm * 128 * IC + off;
            b = g_s16 + (size_t)bn * 128 * IC + off;
            stride = IC;
        } else {
            int koff = (kt - 64) * 64;
            a = g_xo16 + (size_t)bm * 128 * NOUTP + koff;
            b = g_ow16 + (size_t)bn * 128 * NOUTP + koff;
            stride = NOUTP;
        }
        uint32_t st = sbase + s * BSTAGE;
#pragma unroll
        for (int i = 0; i < 4; ++i) {
            int c = tid + i * 256;
            int row = c >> 3, ch = c & 7;
            uint32_t so = (uint32_t)row * 128 + (uint32_t)((ch ^ (row & 7)) << 4);
            CP_ASYNC16(st + so, a + (size_t)row * stride + ch * 8);
            CP_ASYNC16(st + BOFF_B + so, b + (size_t)row * stride + ch * 8);
        }
    };

    auto compute = [&](int s) {
        uint32_t stA = sbase + s * BSTAGE;
        uint32_t stB = stA + BOFF_B;
#pragma unroll
        for (int ks = 0; ks < 4; ++ks) {
            uint32_t bfr[2][4];
#pragma unroll
            for (int nj = 0; nj < 2; ++nj) {
                int row = wn * 32 + nj * 16 + (lane & 7) + (((lane >> 4) & 1) << 3);
                int ch = ks * 2 + ((lane >> 3) & 1);
                uint32_t ad = stB + (uint32_t)row * 128 +
                              (uint32_t)((ch ^ (row & 7)) << 4);
                LDMATRIX_X4(bfr[nj][0], bfr[nj][1], bfr[nj][2], bfr[nj][3], ad);
            }
            uint32_t afr[4][4];
#pragma unroll
            for (int mi = 0; mi < 4; ++mi) {
                int row = wm * 64 + mi * 16 + (lane & 15);
                int ch = ks * 2 + (lane >> 4);
                uint32_t ad = stA + (uint32_t)row * 128 +
                              (uint32_t)((ch ^ (row & 7)) << 4);
                LDMATRIX_X4(afr[mi][0], afr[mi][1], afr[mi][2], afr[mi][3], ad);
            }
#pragma unroll
            for (int mi = 0; mi < 4; ++mi)
#pragma unroll
                for (int nf = 0; nf < 4; ++nf)
                    MMA_F16(acc[mi][nf], afr[mi],
                            bfr[nf >> 1][(nf & 1) * 2],
                            bfr[nf >> 1][(nf & 1) * 2 + 1]);
        }
    };

    issue(0, 0); CP_COMMIT();
    issue(1, 1); CP_COMMIT();
    for (int kt = 0; kt < NT; ++kt) {
        if (kt + 2 < NT) issue(kt + 2, (kt + 2) % 3);
        CP_COMMIT();
        CP_WAIT2();
        __syncthreads();
        compute(kt % 3);
        __syncthreads();
    }

#pragma unroll
    for (int nf = 0; nf < 4; ++nf) {
        int col = bn * 128 + wn * 32 + (nf >> 1) * 16 + (nf & 1) * 8 + 2 * (lane & 3);
        float s0 = g_scale[col], s1 = g_scale[col + 1];
        float b0 = __ldg(bias + col), b1 = __ldg(bias + col + 1);
#pragma unroll
        for (int mi = 0; mi < 4; ++mi) {
            int r0 = bm * 128 + wm * 64 + mi * 16 + (lane >> 2);
            float2 v0 = make_float2(acc[mi][nf][0] * s0 + b0,
                                    acc[mi][nf][1] * s1 + b1);
            *(float2*)(out + (size_t)r0 * OC + col) = v0;
            float2 v1 = make_float2(acc[mi][nf][2] * s0 + b0,
                                    acc[mi][nf][3] * s1 + b1);
            *(float2*)(out + (size_t)(r0 + 8) * OC + col) = v1;
        }
    }
}

// ======================= small GEMM (R7 config, tail tiles) ==================
// CTA 64x128, BK=64, 4 stages, 2 CTAs/SM, one barrier/iter. warp tile 32x32.
static constexpr int SSTAGE = (64 + 128) * 64 * 2;  // 24576
static constexpr int SOFF_B = 64 * 64 * 2;           // 8192
static constexpr int SSMEM  = 4 * SSTAGE;            // 98304

__global__ void __launch_bounds__(256, 2)
gemm_small_kernel(float* __restrict__ out, const float* __restrict__ bias) {
    extern __shared__ __align__(1024) char smem[];
    const uint32_t sbase = smem_u32(smem);
    const int tid = threadIdx.x;
    const int id = N_BIG + (blockIdx.x >> 1);   // tile 888..1023
    const int half = blockIdx.x & 1;
    const int bn = id & 31;
    const int row_base = (id >> 5) * 128 + half * 64;   // 64-row slab
    const int wid = tid >> 5, lane = tid & 31;
    const int wm = wid >> 2, wn = wid & 3;

    float acc[2][4][4];
#pragma unroll
    for (int i = 0; i < 2; ++i)
#pragma unroll
        for (int j = 0; j < 4; ++j)
#pragma unroll
            for (int k = 0; k < 4; ++k) acc[i][j][k] = 0.f;

    auto issue = [&](int kt, int s) {
        const uint16_t *a, *b;
        int stride;
        if (kt < 64) {
            int off = kt * 64;
            a = g_x16 + (size_t)row_base * IC + off;
            b = g_s16 + (size_t)bn * 128 * IC + off;
            stride = IC;
        } else {
            int koff = (kt - 64) * 64;
            a = g_xo16 + (size_t)row_base * NOUTP + koff;
            b = g_ow16 + (size_t)bn * 128 * NOUTP + koff;
            stride = NOUTP;
        }
        uint32_t st = sbase + s * SSTAGE;
#pragma unroll
        for (int i = 0; i < 2; ++i) {
            int c = tid + i * 256;
            int row = c >> 3, ch = c & 7;
            uint32_t so = (uint32_t)row * 128 + (uint32_t)((ch ^ (row & 7)) << 4);
            CP_ASYNC16(st + so, a + (size_t)row * stride + ch * 8);
        }
#pragma unroll
        for (int i = 0; i < 4; ++i) {
            int c = tid + i * 256;
            int row = c >> 3, ch = c & 7;
            uint32_t so = (uint32_t)row * 128 + (uint32_t)((ch ^ (row & 7)) << 4);
            CP_ASYNC16(st + SOFF_B + so, b + (size_t)row * stride + ch * 8);
        }
    };

    auto compute = [&](int s) {
        uint32_t stA = sbase + s * SSTAGE;
        uint32_t stB = stA + SOFF_B;
#pragma unroll
        for (int ks = 0; ks < 4; ++ks) {
            uint32_t bfr[2][4];
#pragma unroll
            for (int nj = 0; nj < 2; ++nj) {
                int row = wn * 32 + nj * 16 + (lane & 7) + (((lane >> 4) & 1) << 3);
                int ch = ks * 2 + ((lane >> 3) & 1);
                uint32_t ad = stB + (uint32_t)row * 128 +
                              (uint32_t)((ch ^ (row & 7)) << 4);
                LDMATRIX_X4(bfr[nj][0], bfr[nj][1], bfr[nj][2], bfr[nj][3], ad);
            }
            uint32_t afr[2][4];
#pragma unroll
            for (int mi = 0; mi < 2; ++mi) {
                int row = wm * 32 + mi * 16 + (lane & 15);
                int ch = ks * 2 + (lane >> 4);
                uint32_t ad = stA + (uint32_t)row * 128 +
                              (uint32_t)((ch ^ (row & 7)) << 4);
                LDMATRIX_X4(afr[mi][0], afr[mi][1], afr[mi][2], afr[mi][3], ad);
            }
#pragma unroll
            for (int mi = 0; mi < 2; ++mi)
#pragma unroll
                for (int nf = 0; nf < 4; ++nf)
                    MMA_F16(acc[mi][nf], afr[mi],
                            bfr[nf >> 1][(nf & 1) * 2],
                            bfr[nf >> 1][(nf & 1) * 2 + 1]);
        }
    };

    issue(0, 0); CP_COMMIT();
    issue(1, 1); CP_COMMIT();
    issue(2, 2); CP_COMMIT();
    for (int kt = 0; kt < NT; ++kt) {
        CP_WAIT2();
        __syncthreads();
        if (kt + 3 < NT) issue(kt + 3, (kt + 3) & 3);
        CP_COMMIT();
        compute(kt & 3);
    }

#pragma unroll
    for (int nf = 0; nf < 4; ++nf) {
        int col = bn * 128 + wn * 32 + (nf >> 1) * 16 + (nf & 1) * 8 + 2 * (lane & 3);
        float s0 = g_scale[col], s1 = g_scale[col + 1];
        float b0 = __ldg(bias + col), b1 = __ldg(bias + col + 1);
#pragma unroll
        for (int mi = 0; mi < 2; ++mi) {
            int r0 = row_base + wm * 32 + mi * 16 + (lane >> 2);
            float2 v0 = make_float2(acc[mi][nf][0] * s0 + b0,
                                    acc[mi][nf][1] * s1 + b1);
            *(float2*)(out + (size_t)r0 * OC + col) = v0;
            float2 v1 = make_float2(acc[mi][nf][2] * s0 + b0,
                                    acc[mi][nf][3] * s1 + b1);
            *(float2*)(out + (size_t)(r0 + 8) * OC + col) = v1;
        }
    }
}

// ======================= launcher ============================================
extern "C" void kernel_launch(void* const* d_in, const int* in_sizes, int n_in,
                              void* d_out, int out_size) {
    const float* x = (const float*)d_in[0];
    const float* w = (const float*)d_in[1];
    const float* bias = (const float*)d_in[2];
    const float* ow = (const float*)d_in[3];
    const int* idx = (const int*)d_in[4];
    float* out = (float*)d_out;
    int nout = in_sizes[4];

    static bool attr_set = false;
    if (!attr_set) {
        cudaFuncSetAttribute(gemm_big_kernel,
                             cudaFuncAttributeMaxDynamicSharedMemorySize, BSMEM);
        cudaFuncSetAttribute(gemm_small_kernel,
                             cudaFuncAttributeMaxDynamicSharedMemorySize, SSMEM);
        attr_set = true;
    }

    map_init_kernel<<<IC / 256, 256>>>();
    map_scatter_kernel<<<(nout + 255) / 256, 256>>>(idx, nout);
    stats_ws_kernel<<<OC, 256>>>(w);
    build_x_kernel<<<(unsigned)((size_t)TOKENS * IC / 2048), 256>>>(x);
    build_xout_kernel<<<TOKENS * NOUTP / 4 / 256, 256>>>(x, idx, nout);
    build_ow_kernel<<<OC * NOUTP / 4 / 256, 256>>>(ow, nout);

    gemm_big_kernel<<<N_BIG, 256, BSMEM>>>(out, bias);
    gemm_small_kernel<<<2 * (1024 - N_BIG), 256, SSMEM>>>(out, bias);
}

// round 9
// speedup vs baseline: 1.1231x; 1.0078x over previous
#include <cuda_runtime.h>
#include <cuda_bf16.h>
#include <cuda_fp16.h>
#include <cstdint>

// ======================= problem sizes (fixed by dataset) ====================
#define TOKENS 4096
#define IC     4096
#define OC     4096
#define NOUTP  256   // outlier columns padded 204 -> 256

// 1024 = 32x32 tiles of 128x128. Tiles [0,888): big path (3.0 waves at
// 2 CTAs/SM x 148 SMs). Tiles [888,1024): split into 2x 64x128 CTAs scheduled
// LAST so they pack into the wave-3 drain (single kernel -> no boundary).
#define N_BIG 888

// ======================= device scratch (no runtime alloc) ==================
__device__ uint16_t g_x16[(size_t)TOKENS * IC];     // 32 MB  x as fp16
__device__ uint16_t g_s16[(size_t)OC * IC];         // 32 MB  sign matrix fp16
__device__ uint16_t g_xo16[(size_t)TOKENS * NOUTP]; // fp16 gathered outlier x
__device__ uint16_t g_ow16[(size_t)OC * NOUTP];     // fp16 (ow / s_o)
__device__ float g_scale[OC];   // 0 -> 1 (exact: then all signs are 0)
__device__ int   g_map[IC];

// ======================= helpers =============================================
__device__ __forceinline__ uint32_t smem_u32(const void* p) {
    uint32_t a;
    asm("{ .reg .u64 t; cvta.to.shared.u64 t, %1; cvt.u32.u64 %0, t; }"
        : "=r"(a) : "l"(p));
    return a;
}

#define CP_ASYNC16(saddr, gaddr) \
    asm volatile("cp.async.cg.shared.global [%0], [%1], 16;" \
                 :: "r"(saddr), "l"(gaddr))
#define CP_COMMIT() asm volatile("cp.async.commit_group;" ::: "memory")
#define CP_WAIT2()  asm volatile("cp.async.wait_group 2;" ::: "memory")

#define LDMATRIX_X4(r0, r1, r2, r3, addr) \
    asm volatile("ldmatrix.sync.aligned.m8n8.x4.shared.b16 {%0,%1,%2,%3}, [%4];" \
                 : "=r"(r0), "=r"(r1), "=r"(r2), "=r"(r3) : "r"(addr))

#define MMA_F16(d, a, b0, b1) \
    asm volatile("mma.sync.aligned.m16n8k16.row.col.f32.f16.f16.f32 " \
                 "{%0,%1,%2,%3}, {%4,%5,%6,%7}, {%8,%9}, {%0,%1,%2,%3};" \
                 : "+f"((d)[0]), "+f"((d)[1]), "+f"((d)[2]), "+f"((d)[3]) \
                 : "r"((a)[0]), "r"((a)[1]), "r"((a)[2]), "r"((a)[3]), \
                   "r"(b0), "r"(b1))

// ======================= prep kernels ========================================
__global__ void map_init_kernel() {
    int i = blockIdx.x * 256 + threadIdx.x;
    if (i < IC) g_map[i] = -1;
}
__global__ void map_scatter_kernel(const int* __restrict__ idx, int nout) {
    int j = blockIdx.x * 256 + threadIdx.x;
    if (j < nout) g_map[idx[j]] = j;
}

// Fused: per-row mean & abs-mean of w + write fp16 sign row (outlier cols 0).
__global__ void stats_ws_kernel(const float* __restrict__ w) {
    __shared__ float red[256];
    int o = blockIdx.x, tid = threadIdx.x;
    const float4* row = (const float4*)(w + (size_t)o * IC);
    float4 v[4];
    float s = 0.f;
#pragma unroll
    for (int i = 0; i < 4; ++i) {
        v[i] = row[tid + 256 * i];
        s += v[i].x + v[i].y + v[i].z + v[i].w;
    }
    red[tid] = s;
    __syncthreads();
    for (int st = 128; st > 0; st >>= 1) {
        if (tid < st) red[tid] += red[tid + st];
        __syncthreads();
    }
    float mean = red[0] * (1.f / IC);
    __syncthreads();
    float a = 0.f;
#pragma unroll
    for (int i = 0; i < 4; ++i)
        a += fabsf(v[i].x - mean) + fabsf(v[i].y - mean) +
             fabsf(v[i].z - mean) + fabsf(v[i].w - mean);
    red[tid] = a;
    __syncthreads();
    for (int st = 128; st > 0; st >>= 1) {
        if (tid < st) red[tid] += red[tid + st];
        __syncthreads();
    }
    if (tid == 0) {
        float sc = red[0] * (1.f / IC);
        g_scale[o] = (sc == 0.f) ? 1.f : sc;
    }
#pragma unroll
    for (int i = 0; i < 4; ++i) {
        int e0 = (tid + 256 * i) * 4;
        float ev[4] = {v[i].x, v[i].y, v[i].z, v[i].w};
        uint16_t hv[4];
#pragma unroll
        for (int e = 0; e < 4; ++e) {
            float sv = 0.f;
            if (g_map[e0 + e] < 0) {
                float wc = ev[e] - mean;
                sv = (wc > 0.f) ? 1.f : ((wc < 0.f) ? -1.f : 0.f);
            }
            hv[e] = __half_as_ushort(__float2half_rn(sv));
        }
        uint2 pk;
        pk.x = (uint32_t)hv[0] | ((uint32_t)hv[1] << 16);
        pk.y = (uint32_t)hv[2] | ((uint32_t)hv[3] << 16);
        *(uint2*)(g_s16 + (size_t)o * IC + e0) = pk;
    }
}

__global__ void build_x_kernel(const float* __restrict__ x) {
    size_t base = ((size_t)blockIdx.x * 256 + threadIdx.x) * 8;
    float4 v0 = *(const float4*)(x + base);
    float4 v1 = *(const float4*)(x + base + 4);
    float e[8] = {v0.x, v0.y, v0.z, v0.w, v1.x, v1.y, v1.z, v1.w};
    uint16_t hv[8];
#pragma unroll
    for (int k = 0; k < 8; ++k) hv[k] = __half_as_ushort(__float2half_rn(e[k]));
    uint4 pk;
    pk.x = (uint32_t)hv[0] | ((uint32_t)hv[1] << 16);
    pk.y = (uint32_t)hv[2] | ((uint32_t)hv[3] << 16);
    pk.z = (uint32_t)hv[4] | ((uint32_t)hv[5] << 16);
    pk.w = (uint32_t)hv[6] | ((uint32_t)hv[7] << 16);
    *(uint4*)(g_x16 + base) = pk;
}

__global__ void build_xout_kernel(const float* __restrict__ x,
                                  const int* __restrict__ idx, int nout) {
    int g = blockIdx.x * 256 + threadIdx.x;
    if (g >= TOKENS * NOUTP / 4) return;
    int tok = g >> 6;
    int j0 = (g & 63) * 4;
    uint16_t hv[4];
#pragma unroll
    for (int e = 0; e < 4; ++e) {
        int j = j0 + e;
        float xv = (j < nout) ? x[(size_t)tok * IC + idx[j]] : 0.f;
        hv[e] = __half_as_ushort(__float2half_rn(xv));
    }
    *(uint2*)(g_xo16 + (size_t)tok * NOUTP + j0) =
        make_uint2((uint32_t)hv[0] | ((uint32_t)hv[1] << 16),
                   (uint32_t)hv[2] | ((uint32_t)hv[3] << 16));
}

__global__ void build_ow_kernel(const float* __restrict__ ow, int nout) {
    int g = blockIdx.x * 256 + threadIdx.x;
    if (g >= OC * NOUTP / 4) return;
    int o = g >> 6;
    int j0 = (g & 63) * 4;
    float inv_s = 1.f / g_scale[o];
    uint16_t hv[4];
#pragma unroll
    for (int e = 0; e < 4; ++e) {
        int j = j0 + e;
        float v = (j < nout) ? ow[(size_t)o * nout + j] * inv_s : 0.f;
        hv[e] = __half_as_ushort(__float2half_rn(v));
    }
    *(uint2*)(g_ow16 + (size_t)o * NOUTP + j0) =
        make_uint2((uint32_t)hv[0] | ((uint32_t)hv[1] << 16),
                   (uint32_t)hv[2] | ((uint32_t)hv[3] << 16));
}

// ======================= unified GEMM ========================================
static constexpr int NT = 68;
// big path: 128x128, BK=64, 3 stages
static constexpr int BSTAGE = (128 + 128) * 64 * 2;  // 32768
static constexpr int BOFF_B = 128 * 64 * 2;           // 16384
// small path: 64x128, BK=64, 4 stages
static constexpr int SSTAGE = (64 + 128) * 64 * 2;   // 24576
static constexpr int SOFF_B = 64 * 64 * 2;            // 8192
static constexpr int GSMEM  = 3 * BSTAGE;             // 98304 (= 4*SSTAGE)

__global__ void __launch_bounds__(256, 2)
gemm_kernel(float* __restrict__ out, const float* __restrict__ bias) {
    extern __shared__ __align__(1024) char smem[];
    const uint32_t sbase = smem_u32(smem);
    const int tid = threadIdx.x;
    const int wid = tid >> 5, lane = tid & 31;
    const int wm = wid >> 2, wn = wid & 3;

    if (blockIdx.x < N_BIG) {
        // ================= big path: 128x128 =================
        const int id = blockIdx.x;
        const int bm = id >> 5, bn = id & 31;

        float acc[4][4][4];
#pragma unroll
        for (int i = 0; i < 4; ++i)
#pragma unroll
            for (int j = 0; j < 4; ++j)
#pragma unroll
                for (int k = 0; k < 4; ++k) acc[i][j][k] = 0.f;

        auto issue = [&](int kt, int s) {
            const uint16_t *a, *b;
            int stride;
            if (kt < 64) {
                int off = kt * 64;
                a = g_x16 + (size_t)bm * 128 * IC + off;
                b = g_s16 + (size_t)bn * 128 * IC + off;
                stride = IC;
            } else {
                int koff = (kt - 64) * 64;
                a = g_xo16 + (size_t)bm * 128 * NOUTP + koff;
                b = g_ow16 + (size_t)bn * 128 * NOUTP + koff;
                stride = NOUTP;
            }
            uint32_t st = sbase + s * BSTAGE;
#pragma unroll
            for (int i = 0; i < 4; ++i) {
                int c = tid + i * 256;
                int row = c >> 3, ch = c & 7;
                uint32_t so = (uint32_t)row * 128 + (uint32_t)((ch ^ (row & 7)) << 4);
                CP_ASYNC16(st + so, a + (size_t)row * stride + ch * 8);
                CP_ASYNC16(st + BOFF_B + so, b + (size_t)row * stride + ch * 8);
            }
        };

        auto compute = [&](int s) {
            uint32_t stA = sbase + s * BSTAGE;
            uint32_t stB = stA + BOFF_B;
#pragma unroll
            for (int ks = 0; ks < 4; ++ks) {
                uint32_t bfr[2][4];
#pragma unroll
                for (int nj = 0; nj < 2; ++nj) {
                    int row = wn * 32 + nj * 16 + (lane & 7) + (((lane >> 4) & 1) << 3);
                    int ch = ks * 2 + ((lane >> 3) & 1);
                    uint32_t ad = stB + (uint32_t)row * 128 +
                                  (uint32_t)((ch ^ (row & 7)) << 4);
                    LDMATRIX_X4(bfr[nj][0], bfr[nj][1], bfr[nj][2], bfr[nj][3], ad);
                }
                uint32_t afr[4][4];
#pragma unroll
                for (int mi = 0; mi < 4; ++mi) {
                    int row = wm * 64 + mi * 16 + (lane & 15);
                    int ch = ks * 2 + (lane >> 4);
                    uint32_t ad = stA + (uint32_t)row * 128 +
                                  (uint32_t)((ch ^ (row & 7)) << 4);
                    LDMATRIX_X4(afr[mi][0], afr[mi][1], afr[mi][2], afr[mi][3], ad);
                }
#pragma unroll
                for (int mi = 0; mi < 4; ++mi)
#pragma unroll
                    for (int nf = 0; nf < 4; ++nf)
                        MMA_F16(acc[mi][nf], afr[mi],
                                bfr[nf >> 1][(nf & 1) * 2],
                                bfr[nf >> 1][(nf & 1) * 2 + 1]);
            }
        };

        issue(0, 0); CP_COMMIT();
        issue(1, 1); CP_COMMIT();
        for (int kt = 0; kt < NT; ++kt) {
            if (kt + 2 < NT) issue(kt + 2, (kt + 2) % 3);
            CP_COMMIT();
            CP_WAIT2();
            __syncthreads();
            compute(kt % 3);
            __syncthreads();
        }

#pragma unroll
        for (int nf = 0; nf < 4; ++nf) {
            int col = bn * 128 + wn * 32 + (nf >> 1) * 16 + (nf & 1) * 8 + 2 * (lane & 3);
            float s0 = g_scale[col], s1 = g_scale[col + 1];
            float b0 = __ldg(bias + col), b1 = __ldg(bias + col + 1);
#pragma unroll
            for (int mi = 0; mi < 4; ++mi) {
                int r0 = bm * 128 + wm * 64 + mi * 16 + (lane >> 2);
                float2 v0 = make_float2(acc[mi][nf][0] * s0 + b0,
                                        acc[mi][nf][1] * s1 + b1);
                *(float2*)(out + (size_t)r0 * OC + col) = v0;
                float2 v1 = make_float2(acc[mi][nf][2] * s0 + b0,
                                        acc[mi][nf][3] * s1 + b1);
                *(float2*)(out + (size_t)(r0 + 8) * OC + col) = v1;
            }
        }
    } else {
        // ================= small path: 64x128 (tail tiles) =================
        const int sid = blockIdx.x - N_BIG;          // 0..271
        const int id = N_BIG + (sid >> 1);           // tile 888..1023
        const int half = sid & 1;
        const int bn = id & 31;
        const int row_base = (id >> 5) * 128 + half * 64;

        float acc[2][4][4];
#pragma unroll
        for (int i = 0; i < 2; ++i)
#pragma unroll
            for (int j = 0; j < 4; ++j)
#pragma unroll
                for (int k = 0; k < 4; ++k) acc[i][j][k] = 0.f;

        auto issue = [&](int kt, int s) {
            const uint16_t *a, *b;
            int stride;
            if (kt < 64) {
                int off = kt * 64;
                a = g_x16 + (size_t)row_base * IC + off;
                b = g_s16 + (size_t)bn * 128 * IC + off;
                stride = IC;
            } else {
                int koff = (kt - 64) * 64;
                a = g_xo16 + (size_t)row_base * NOUTP + koff;
                b = g_ow16 + (size_t)bn * 128 * NOUTP + koff;
                stride = NOUTP;
            }
            uint32_t st = sbase + s * SSTAGE;
#pragma unroll
            for (int i = 0; i < 2; ++i) {
                int c = tid + i * 256;
                int row = c >> 3, ch = c & 7;
                uint32_t so = (uint32_t)row * 128 + (uint32_t)((ch ^ (row & 7)) << 4);
                CP_ASYNC16(st + so, a + (size_t)row * stride + ch * 8);
            }
#pragma unroll
            for (int i = 0; i < 4; ++i) {
                int c = tid + i * 256;
                int row = c >> 3, ch = c & 7;
                uint32_t so = (uint32_t)row * 128 + (uint32_t)((ch ^ (row & 7)) << 4);
                CP_ASYNC16(st + SOFF_B + so, b + (size_t)row * stride + ch * 8);
            }
        };

        auto compute = [&](int s) {
            uint32_t stA = sbase + s * SSTAGE;
            uint32_t stB = stA + SOFF_B;
#pragma unroll
            for (int ks = 0; ks < 4; ++ks) {
                uint32_t bfr[2][4];
#pragma unroll
                for (int nj = 0; nj < 2; ++nj) {
                    int row = wn * 32 + nj * 16 + (lane & 7) + (((lane >> 4) & 1) << 3);
                    int ch = ks * 2 + ((lane >> 3) & 1);
                    uint32_t ad = stB + (uint32_t)row * 128 +
                                  (uint32_t)((ch ^ (row & 7)) << 4);
                    LDMATRIX_X4(bfr[nj][0], bfr[nj][1], bfr[nj][2], bfr[nj][3], ad);
                }
                uint32_t afr[2][4];
#pragma unroll
                for (int mi = 0; mi < 2; ++mi) {
                    int row = wm * 32 + mi * 16 + (lane & 15);
                    int ch = ks * 2 + (lane >> 4);
                    uint32_t ad = stA + (uint32_t)row * 128 +
                                  (uint32_t)((ch ^ (row & 7)) << 4);
                    LDMATRIX_X4(afr[mi][0], afr[mi][1], afr[mi][2], afr[mi][3], ad);
                }
#pragma unroll
                for (int mi = 0; mi < 2; ++mi)
#pragma unroll
                    for (int nf = 0; nf < 4; ++nf)
                        MMA_F16(acc[mi][nf], afr[mi],
                                bfr[nf >> 1][(nf & 1) * 2],
                                bfr[nf >> 1][(nf & 1) * 2 + 1]);
            }
        };

        issue(0, 0); CP_COMMIT();
        issue(1, 1); CP_COMMIT();
        issue(2, 2); CP_COMMIT();
        for (int kt = 0; kt < NT; ++kt) {
            CP_WAIT2();
            __syncthreads();
            if (kt + 3 < NT) issue(kt + 3, (kt + 3) & 3);
            CP_COMMIT();
            compute(kt & 3);
        }

#pragma unroll
        for (int nf = 0; nf < 4; ++nf) {
            int col = bn * 128 + wn * 32 + (nf >> 1) * 16 + (nf & 1) * 8 + 2 * (lane & 3);
            float s0 = g_scale[col], s1 = g_scale[col + 1];
            float b0 = __ldg(bias + col), b1 = __ldg(bias + col + 1);
#pragma unroll
            for (int mi = 0; mi < 2; ++mi) {
                int r0 = row_base + wm * 32 + mi * 16 + (lane >> 2);
                float2 v0 = make_float2(acc[mi][nf][0] * s0 + b0,
                                        acc[mi][nf][1] * s1 + b1);
                *(float2*)(out + (size_t)r0 * OC + col) = v0;
                float2 v1 = make_float2(acc[mi][nf][2] * s0 + b0,
                                        acc[mi][nf][3] * s1 + b1);
                *(float2*)(out + (size_t)(r0 + 8) * OC + col) = v1;
            }
        }
    }
}

// ======================= launcher ============================================
extern "C" void kernel_launch(void* const* d_in, const int* in_sizes, int n_in,
                              void* d_out, int out_size) {
    const float* x = (const float*)d_in[0];
    const float* w = (const float*)d_in[1];
    const float* bias = (const float*)d_in[2];
    const float* ow = (const float*)d_in[3];
    const int* idx = (const int*)d_in[4];
    float* out = (float*)d_out;
    int nout = in_sizes[4];

    static bool attr_set = false;
    if (!attr_set) {
        cudaFuncSetAttribute(gemm_kernel,
                             cudaFuncAttributeMaxDynamicSharedMemorySize, GSMEM);
        attr_set = true;
    }

    map_init_kernel<<<IC / 256, 256>>>();
    map_scatter_kernel<<<(nout + 255) / 256, 256>>>(idx, nout);
    stats_ws_kernel<<<OC, 256>>>(w);
    build_x_kernel<<<(unsigned)((size_t)TOKENS * IC / 2048), 256>>>(x);
    build_xout_kernel<<<TOKENS * NOUTP / 4 / 256, 256>>>(x, idx, nout);
    build_ow_kernel<<<OC * NOUTP / 4 / 256, 256>>>(ow, nout);

    gemm_kernel<<<N_BIG + 2 * (1024 - N_BIG), 256, GSMEM>>>(out, bias);
}

// round 10
// speedup vs baseline: 1.2316x; 1.0966x over previous
#include <cuda_runtime.h>
#include <cuda_bf16.h>
#include <cuda_fp16.h>
#include <cstdint>

// ======================= problem sizes (fixed by dataset) ====================
#define TOKENS 4096
#define IC     4096
#define OC     4096

// ======================= device scratch (no runtime alloc) ==================
__device__ uint16_t g_x16[(size_t)TOKENS * IC];  // 32 MB  x as fp16
__device__ uint16_t g_s16[(size_t)OC * IC];      // 32 MB  B = sign / (ow/s) fp16
__device__ float g_scale[OC];   // 0 -> 1 (exact: then all signs are 0)
__device__ int   g_map[IC];

// ======================= helpers =============================================
__device__ __forceinline__ uint32_t smem_u32(const void* p) {
    uint32_t a;
    asm("{ .reg .u64 t; cvta.to.shared.u64 t, %1; cvt.u32.u64 %0, t; }"
        : "=r"(a) : "l"(p));
    return a;
}

#define CP_ASYNC16(saddr, gaddr) \
    asm volatile("cp.async.cg.shared.global [%0], [%1], 16;" \
                 :: "r"(saddr), "l"(gaddr))
#define CP_COMMIT() asm volatile("cp.async.commit_group;" ::: "memory")
#define CP_WAIT2()  asm volatile("cp.async.wait_group 2;" ::: "memory")

#define LDMATRIX_X4(r0, r1, r2, r3, addr) \
    asm volatile("ldmatrix.sync.aligned.m8n8.x4.shared.b16 {%0,%1,%2,%3}, [%4];" \
                 : "=r"(r0), "=r"(r1), "=r"(r2), "=r"(r3) : "r"(addr))

#define MMA_F16(d, a, b0, b1) \
    asm volatile("mma.sync.aligned.m16n8k16.row.col.f32.f16.f16.f32 " \
                 "{%0,%1,%2,%3}, {%4,%5,%6,%7}, {%8,%9}, {%0,%1,%2,%3};" \
                 : "+f"((d)[0]), "+f"((d)[1]), "+f"((d)[2]), "+f"((d)[3]) \
                 : "r"((a)[0]), "r"((a)[1]), "r"((a)[2]), "r"((a)[3]), \
                   "r"(b0), "r"(b1))

// ======================= prep kernels ========================================
__global__ void map_init_kernel() {
    int i = blockIdx.x * 256 + threadIdx.x;
    if (i < IC) g_map[i] = -1;
}
__global__ void map_scatter_kernel(const int* __restrict__ idx, int nout) {
    int j = blockIdx.x * 256 + threadIdx.x;
    if (j < nout) g_map[idx[j]] = j;
}

// Fused: per-row mean & abs-mean of w + write fp16 B row:
//   non-outlier col: sign(w - mean) in {-1,0,1}
//   outlier col    : ow[o, slot] / s_eff   (folded outlier weights)
// Epilogue multiplies by s_eff, recovering sign*scale and ow exactly.
__global__ void stats_ws_kernel(const float* __restrict__ w,
                                const float* __restrict__ ow, int nout) {
    __shared__ float red[256];
    int o = blockIdx.x, tid = threadIdx.x;
    const float4* row = (const float4*)(w + (size_t)o * IC);
    float4 v[4];
    float s = 0.f;
#pragma unroll
    for (int i = 0; i < 4; ++i) {
        v[i] = row[tid + 256 * i];
        s += v[i].x + v[i].y + v[i].z + v[i].w;
    }
    red[tid] = s;
    __syncthreads();
    for (int st = 128; st > 0; st >>= 1) {
        if (tid < st) red[tid] += red[tid + st];
        __syncthreads();
    }
    float mean = red[0] * (1.f / IC);
    __syncthreads();
    float a = 0.f;
#pragma unroll
    for (int i = 0; i < 4; ++i)
        a += fabsf(v[i].x - mean) + fabsf(v[i].y - mean) +
             fabsf(v[i].z - mean) + fabsf(v[i].w - mean);
    red[tid] = a;
    __syncthreads();
    for (int st = 128; st > 0; st >>= 1) {
        if (tid < st) red[tid] += red[tid + st];
        __syncthreads();
    }
    float sc = red[0] * (1.f / IC);
    float s_eff = (sc == 0.f) ? 1.f : sc;
    if (tid == 0) g_scale[o] = s_eff;
    float inv_s = 1.f / s_eff;
    const float* ow_row = ow + (size_t)o * nout;
#pragma unroll
    for (int i = 0; i < 4; ++i) {
        int e0 = (tid + 256 * i) * 4;
        float ev[4] = {v[i].x, v[i].y, v[i].z, v[i].w};
        uint16_t hv[4];
#pragma unroll
        for (int e = 0; e < 4; ++e) {
            int slot = g_map[e0 + e];
            float sv;
            if (slot < 0) {
                float wc = ev[e] - mean;
                sv = (wc > 0.f) ? 1.f : ((wc < 0.f) ? -1.f : 0.f);
            } else {
                sv = ow_row[slot] * inv_s;
            }
            hv[e] = __half_as_ushort(__float2half_rn(sv));
        }
        uint2 pk;
        pk.x = (uint32_t)hv[0] | ((uint32_t)hv[1] << 16);
        pk.y = (uint32_t)hv[2] | ((uint32_t)hv[3] << 16);
        *(uint2*)(g_s16 + (size_t)o * IC + e0) = pk;
    }
}

__global__ void build_x_kernel(const float* __restrict__ x) {
    size_t base = ((size_t)blockIdx.x * 256 + threadIdx.x) * 8;
    float4 v0 = *(const float4*)(x + base);
    float4 v1 = *(const float4*)(x + base + 4);
    float e[8] = {v0.x, v0.y, v0.z, v0.w, v1.x, v1.y, v1.z, v1.w};
    uint16_t hv[8];
#pragma unroll
    for (int k = 0; k < 8; ++k) hv[k] = __half_as_ushort(__float2half_rn(e[k]));
    uint4 pk;
    pk.x = (uint32_t)hv[0] | ((uint32_t)hv[1] << 16);
    pk.y = (uint32_t)hv[2] | ((uint32_t)hv[3] << 16);
    pk.z = (uint32_t)hv[4] | ((uint32_t)hv[5] << 16);
    pk.w = (uint32_t)hv[6] | ((uint32_t)hv[7] << 16);
    *(uint4*)(g_x16 + base) = pk;
}

// ======================= GEMM (R6 config) ====================================
// CTA 128x128, BK=64, 3 stages, 2 CTAs/SM. 8 warps (2m x 4n), warp tile 64x32.
// K = 4096 (outliers folded into B). Epilogue: out = acc * s_o + bias.
static constexpr int NT = 64;
static constexpr int STAGE_BYTES = (128 + 128) * 64 * 2;  // 32768
static constexpr int OFF_B = 128 * 64 * 2;                 // 16384
static constexpr int SMEM_BYTES = 3 * STAGE_BYTES;         // 98304

__global__ void __launch_bounds__(256, 2)
gemm_kernel(float* __restrict__ out, const float* __restrict__ bias) {
    extern __shared__ __align__(1024) char smem[];
    const uint32_t sbase = smem_u32(smem);
    const int tid = threadIdx.x;
    const int bn = blockIdx.x, bm = blockIdx.y;
    const int wid = tid >> 5, lane = tid & 31;
    const int wm = wid >> 2, wn = wid & 3;

    float acc[4][4][4];
#pragma unroll
    for (int i = 0; i < 4; ++i)
#pragma unroll
        for (int j = 0; j < 4; ++j)
#pragma unroll
            for (int k = 0; k < 4; ++k) acc[i][j][k] = 0.f;

    const uint16_t* Abase = g_x16 + (size_t)bm * 128 * IC;
    const uint16_t* Bbase = g_s16 + (size_t)bn * 128 * IC;

    auto issue = [&](int kt, int s) {
        const uint16_t* a = Abase + kt * 64;
        const uint16_t* b = Bbase + kt * 64;
        uint32_t st = sbase + s * STAGE_BYTES;
#pragma unroll
        for (int i = 0; i < 4; ++i) {
            int c = tid + i * 256;
            int row = c >> 3, ch = c & 7;
            uint32_t so = (uint32_t)row * 128 + (uint32_t)((ch ^ (row & 7)) << 4);
            CP_ASYNC16(st + so, a + (size_t)row * IC + ch * 8);
            CP_ASYNC16(st + OFF_B + so, b + (size_t)row * IC + ch * 8);
        }
    };

    auto compute = [&](int s) {
        uint32_t stA = sbase + s * STAGE_BYTES;
        uint32_t stB = stA + OFF_B;
#pragma unroll
        for (int ks = 0; ks < 4; ++ks) {
            uint32_t bfr[2][4];
#pragma unroll
            for (int nj = 0; nj < 2; ++nj) {
                int row = wn * 32 + nj * 16 + (lane & 7) + (((lane >> 4) & 1) << 3);
                int ch = ks * 2 + ((lane >> 3) & 1);
                uint32_t ad = stB + (uint32_t)row * 128 +
                              (uint32_t)((ch ^ (row & 7)) << 4);
                LDMATRIX_X4(bfr[nj][0], bfr[nj][1], bfr[nj][2], bfr[nj][3], ad);
            }
            uint32_t afr[4][4];
#pragma unroll
            for (int mi = 0; mi < 4; ++mi) {
                int row = wm * 64 + mi * 16 + (lane & 15);
                int ch = ks * 2 + (lane >> 4);
                uint32_t ad = stA + (uint32_t)row * 128 +
                              (uint32_t)((ch ^ (row & 7)) << 4);
                LDMATRIX_X4(afr[mi][0], afr[mi][1], afr[mi][2], afr[mi][3], ad);
            }
#pragma unroll
            for (int mi = 0; mi < 4; ++mi)
#pragma unroll
                for (int nf = 0; nf < 4; ++nf)
                    MMA_F16(acc[mi][nf], afr[mi],
                            bfr[nf >> 1][(nf & 1) * 2],
                            bfr[nf >> 1][(nf & 1) * 2 + 1]);
        }
    };

    issue(0, 0); CP_COMMIT();
    issue(1, 1); CP_COMMIT();
    for (int kt = 0; kt < NT; ++kt) {
        if (kt + 2 < NT) issue(kt + 2, (kt + 2) % 3);
        CP_COMMIT();
        CP_WAIT2();
        __syncthreads();
        compute(kt % 3);
        __syncthreads();
    }

    // ---- epilogue: out = acc * s_o + bias ------------------------------
#pragma unroll
    for (int nf = 0; nf < 4; ++nf) {
        int col = bn * 128 + wn * 32 + (nf >> 1) * 16 + (nf & 1) * 8 + 2 * (lane & 3);
        float s0 = g_scale[col], s1 = g_scale[col + 1];
        float b0 = __ldg(bias + col), b1 = __ldg(bias + col + 1);
#pragma unroll
        for (int mi = 0; mi < 4; ++mi) {
            int r0 = bm * 128 + wm * 64 + mi * 16 + (lane >> 2);
            float2 v0 = make_float2(acc[mi][nf][0] * s0 + b0,
                                    acc[mi][nf][1] * s1 + b1);
            *(float2*)(out + (size_t)r0 * OC + col) = v0;
            float2 v1 = make_float2(acc[mi][nf][2] * s0 + b0,
                                    acc[mi][nf][3] * s1 + b1);
            *(float2*)(out + (size_t)(r0 + 8) * OC + col) = v1;
        }
    }
}

// ======================= launcher ============================================
extern "C" void kernel_launch(void* const* d_in, const int* in_sizes, int n_in,
                              void* d_out, int out_size) {
    const float* x = (const float*)d_in[0];
    const float* w = (const float*)d_in[1];
    const float* bias = (const float*)d_in[2];
    const float* ow = (const float*)d_in[3];
    const int* idx = (const int*)d_in[4];
    float* out = (float*)d_out;
    int nout = in_sizes[4];

    static bool attr_set = false;
    if (!attr_set) {
        cudaFuncSetAttribute(gemm_kernel,
                             cudaFuncAttributeMaxDynamicSharedMemorySize, SMEM_BYTES);
        attr_set = true;
    }

    map_init_kernel<<<IC / 256, 256>>>();
    map_scatter_kernel<<<(nout + 255) / 256, 256>>>(idx, nout);
    stats_ws_kernel<<<OC, 256>>>(w, ow, nout);
    build_x_kernel<<<(unsigned)((size_t)TOKENS * IC / 2048), 256>>>(x);

    dim3 grid(OC / 128, TOKENS / 128);
    gemm_kernel<<<grid, 256, SMEM_BYTES>>>(out, bias);
}